// round 14
// baseline (speedup 1.0000x reference)
#include <cuda_runtime.h>
#include <math.h>

// SoftArgmax over (B=32, C=64, H=256, W=256) fp32 heatmap.
// Outputs concatenated: coords (B,C,2) | cov (B,C,2,2) | spread (B,C,1)
//   = 4096 + 8192 + 2048 = 14336 floats.
//
// FINAL FORM (best measured: 80.6us; reproduced 4x at 80.6-81.4us, sigma
// ~0.4us). One block per (b,c), 256 threads, occ 8 (64 warps/SM). The scan
// streams 536 MB at ~6.7 TB/s, pinned at the B300 full-chip LTS throughput
// cap (~6300 B/cyc, path-independent) — invariant across ILP / occupancy /
// launch-structure variants (R4-R7). Hard floor ~79.2us; no measured
// alternative came closer than this configuration.
// Phase 1: float4 argmax scan, lowest-index tie-break (jnp.argmax semantics).
// Phase 2: masked softmax over the clamped 16x16 window, moments relative
// to (x0,y0) for fp32 accuracy; window reloads hit L2.

#define HW 65536
#define W 256
#define H 256
#define HALF 8
#define NTHREADS 256
#define INV_TEMP 100.0f   // 1 / 0.01

__global__ __launch_bounds__(NTHREADS)
void softargmax_kernel(const float* __restrict__ heatmap, float* __restrict__ out, int n_bc)
{
    int bc = blockIdx.x;
    if (bc >= n_bc) return;
    const float* base = heatmap + (size_t)bc * HW;

    int tid  = threadIdx.x;
    int lane = tid & 31;
    int warp = tid >> 5;

    // ---------------- Phase 1: argmax (lowest-index tie-break) ----------------
    float best = -INFINITY;
    int   bidx = 0;

    const float4* p4 = (const float4*)base;
    #pragma unroll 4
    for (int i = tid; i < HW / 4; i += NTHREADS) {
        float4 v = __ldg(&p4[i]);
        int ib = i * 4;
        if (v.x > best || (v.x == best && ib + 0 < bidx)) { best = v.x; bidx = ib + 0; }
        if (v.y > best || (v.y == best && ib + 1 < bidx)) { best = v.y; bidx = ib + 1; }
        if (v.z > best || (v.z == best && ib + 2 < bidx)) { best = v.z; bidx = ib + 2; }
        if (v.w > best || (v.w == best && ib + 3 < bidx)) { best = v.w; bidx = ib + 3; }
    }

    // warp reduction
    #pragma unroll
    for (int off = 16; off > 0; off >>= 1) {
        float ov = __shfl_down_sync(0xffffffffu, best, off);
        int   oi = __shfl_down_sync(0xffffffffu, bidx, off);
        if (ov > best || (ov == best && oi < bidx)) { best = ov; bidx = oi; }
    }

    __shared__ float s_wval[8];
    __shared__ int   s_widx[8];
    __shared__ int   s_argmax;
    __shared__ float s_vmax;

    if (lane == 0) { s_wval[warp] = best; s_widx[warp] = bidx; }
    __syncthreads();

    if (tid == 0) {
        float bv = s_wval[0]; int bi = s_widx[0];
        #pragma unroll
        for (int w = 1; w < 8; w++) {
            float ov = s_wval[w]; int oi = s_widx[w];
            if (ov > bv || (ov == bv && oi < bi)) { bv = ov; bi = oi; }
        }
        s_argmax = bi;
        s_vmax   = bv;
    }
    __syncthreads();

    int   idx  = s_argmax;
    float vmax = s_vmax;
    int x0 = idx & (W - 1);
    int y0 = idx >> 8;

    int xmin = max(x0 - HALF, 0);
    int xmax = min(x0 + HALF, W);
    int ymin = max(y0 - HALF, 0);
    int ymax = min(y0 + HALF, H);
    int wx = xmax - xmin;
    int wy = ymax - ymin;

    // ---------------- Phase 2: windowed softmax moments ----------------
    // thread (ly, lx) = (tid/16, tid%16) covers window cell (ymin+ly, xmin+lx)
    int lx = tid & 15;
    int ly = tid >> 4;

    float e = 0.f, sdx = 0.f, sdy = 0.f, sdxx = 0.f, sdyy = 0.f, sdxy = 0.f;
    if (lx < wx && ly < wy) {
        int gx = xmin + lx;
        int gy = ymin + ly;
        float v = __ldg(&base[gy * W + gx]);
        float w8 = expf((v - vmax) * INV_TEMP);
        float dx = (float)(gx - x0);
        float dy = (float)(gy - y0);
        e    = w8;
        sdx  = w8 * dx;
        sdy  = w8 * dy;
        sdxx = w8 * dx * dx;
        sdyy = w8 * dy * dy;
        sdxy = w8 * dx * dy;
    }

    // reduce 6 sums: warp shuffle then cross-warp via shared
    #pragma unroll
    for (int off = 16; off > 0; off >>= 1) {
        e    += __shfl_down_sync(0xffffffffu, e,    off);
        sdx  += __shfl_down_sync(0xffffffffu, sdx,  off);
        sdy  += __shfl_down_sync(0xffffffffu, sdy,  off);
        sdxx += __shfl_down_sync(0xffffffffu, sdxx, off);
        sdyy += __shfl_down_sync(0xffffffffu, sdyy, off);
        sdxy += __shfl_down_sync(0xffffffffu, sdxy, off);
    }

    __shared__ float s_red[8][6];
    if (lane == 0) {
        s_red[warp][0] = e;    s_red[warp][1] = sdx;  s_red[warp][2] = sdy;
        s_red[warp][3] = sdxx; s_red[warp][4] = sdyy; s_red[warp][5] = sdxy;
    }
    __syncthreads();

    if (tid == 0) {
        float S = 0.f, Sx = 0.f, Sy = 0.f, Sxx = 0.f, Syy = 0.f, Sxy = 0.f;
        #pragma unroll
        for (int w = 0; w < 8; w++) {
            S   += s_red[w][0]; Sx  += s_red[w][1]; Sy  += s_red[w][2];
            Sxx += s_red[w][3]; Syy += s_red[w][4]; Sxy += s_red[w][5];
        }
        float inv = 1.0f / S;
        float mdx = Sx * inv;             // E[dx]
        float mdy = Sy * inv;             // E[dy]
        float var_xx = Sxx * inv - mdx * mdx;
        float var_yy = Syy * inv - mdy * mdy;
        float cov_xy = Sxy * inv - mdx * mdy;

        float x_mean = (float)x0 + mdx;
        float y_mean = (float)y0 + mdy;

        // coords (B,C,2) at [0, 4096)
        out[bc * 2 + 0] = x_mean * (1.0f / (W - 1));
        out[bc * 2 + 1] = y_mean * (1.0f / (H - 1));
        // cov (B,C,2,2) at [4096, 12288)
        float* covp = out + 2 * 2048 + bc * 4;
        covp[0] = var_xx;
        covp[1] = cov_xy;
        covp[2] = cov_xy;
        covp[3] = var_yy;
        // spread (B,C,1) at [12288, 14336)
        out[2 * 2048 + 4 * 2048 + bc] = var_xx + var_yy;
    }
}

extern "C" void kernel_launch(void* const* d_in, const int* in_sizes, int n_in,
                              void* d_out, int out_size)
{
    const float* heatmap = (const float*)d_in[0];
    float* out = (float*)d_out;
    int n_bc = in_sizes[0] / HW;   // 32*64 = 2048
    softargmax_kernel<<<n_bc, NTHREADS>>>(heatmap, out, n_bc);
}

// round 15
// speedup vs baseline: 1.0796x; 1.0796x over previous
#include <cuda_runtime.h>
#include <math.h>

// SoftArgmax over (B=32, C=64, H=256, W=256) fp32 heatmap.
// Outputs concatenated: coords (B,C,2) | cov (B,C,2,2) | spread (B,C,1)
//   = 4096 + 8192 + 2048 = 14336 floats.
//
// FINAL FORM (best measured: 80.6us; reproduced at 80.6-81.4us, sigma
// ~0.4us; one 86.8us DVFS outlier with a depressed-clock ncu signature).
// One block per (b,c), 256 threads, occ 8 (64 warps/SM). The scan streams
// 536 MB at ~6.7 TB/s, pinned at the B300 full-chip LTS throughput cap
// (~6300 B/cyc, path-independent) — invariant across ILP / occupancy /
// launch-structure variants (R4-R7). Hard floor ~79.2us; no measured
// alternative came closer than this configuration.
// Phase 1: float4 argmax scan, lowest-index tie-break (jnp.argmax semantics).
// Phase 2: masked softmax over the clamped 16x16 window, moments relative
// to (x0,y0) for fp32 accuracy; window reloads hit L2.

#define HW 65536
#define W 256
#define H 256
#define HALF 8
#define NTHREADS 256
#define INV_TEMP 100.0f   // 1 / 0.01

__global__ __launch_bounds__(NTHREADS)
void softargmax_kernel(const float* __restrict__ heatmap, float* __restrict__ out, int n_bc)
{
    int bc = blockIdx.x;
    if (bc >= n_bc) return;
    const float* base = heatmap + (size_t)bc * HW;

    int tid  = threadIdx.x;
    int lane = tid & 31;
    int warp = tid >> 5;

    // ---------------- Phase 1: argmax (lowest-index tie-break) ----------------
    float best = -INFINITY;
    int   bidx = 0;

    const float4* p4 = (const float4*)base;
    #pragma unroll 4
    for (int i = tid; i < HW / 4; i += NTHREADS) {
        float4 v = __ldg(&p4[i]);
        int ib = i * 4;
        if (v.x > best || (v.x == best && ib + 0 < bidx)) { best = v.x; bidx = ib + 0; }
        if (v.y > best || (v.y == best && ib + 1 < bidx)) { best = v.y; bidx = ib + 1; }
        if (v.z > best || (v.z == best && ib + 2 < bidx)) { best = v.z; bidx = ib + 2; }
        if (v.w > best || (v.w == best && ib + 3 < bidx)) { best = v.w; bidx = ib + 3; }
    }

    // warp reduction
    #pragma unroll
    for (int off = 16; off > 0; off >>= 1) {
        float ov = __shfl_down_sync(0xffffffffu, best, off);
        int   oi = __shfl_down_sync(0xffffffffu, bidx, off);
        if (ov > best || (ov == best && oi < bidx)) { best = ov; bidx = oi; }
    }

    __shared__ float s_wval[8];
    __shared__ int   s_widx[8];
    __shared__ int   s_argmax;
    __shared__ float s_vmax;

    if (lane == 0) { s_wval[warp] = best; s_widx[warp] = bidx; }
    __syncthreads();

    if (tid == 0) {
        float bv = s_wval[0]; int bi = s_widx[0];
        #pragma unroll
        for (int w = 1; w < 8; w++) {
            float ov = s_wval[w]; int oi = s_widx[w];
            if (ov > bv || (ov == bv && oi < bi)) { bv = ov; bi = oi; }
        }
        s_argmax = bi;
        s_vmax   = bv;
    }
    __syncthreads();

    int   idx  = s_argmax;
    float vmax = s_vmax;
    int x0 = idx & (W - 1);
    int y0 = idx >> 8;

    int xmin = max(x0 - HALF, 0);
    int xmax = min(x0 + HALF, W);
    int ymin = max(y0 - HALF, 0);
    int ymax = min(y0 + HALF, H);
    int wx = xmax - xmin;
    int wy = ymax - ymin;

    // ---------------- Phase 2: windowed softmax moments ----------------
    // thread (ly, lx) = (tid/16, tid%16) covers window cell (ymin+ly, xmin+lx)
    int lx = tid & 15;
    int ly = tid >> 4;

    float e = 0.f, sdx = 0.f, sdy = 0.f, sdxx = 0.f, sdyy = 0.f, sdxy = 0.f;
    if (lx < wx && ly < wy) {
        int gx = xmin + lx;
        int gy = ymin + ly;
        float v = __ldg(&base[gy * W + gx]);
        float w8 = expf((v - vmax) * INV_TEMP);
        float dx = (float)(gx - x0);
        float dy = (float)(gy - y0);
        e    = w8;
        sdx  = w8 * dx;
        sdy  = w8 * dy;
        sdxx = w8 * dx * dx;
        sdyy = w8 * dy * dy;
        sdxy = w8 * dx * dy;
    }

    // reduce 6 sums: warp shuffle then cross-warp via shared
    #pragma unroll
    for (int off = 16; off > 0; off >>= 1) {
        e    += __shfl_down_sync(0xffffffffu, e,    off);
        sdx  += __shfl_down_sync(0xffffffffu, sdx,  off);
        sdy  += __shfl_down_sync(0xffffffffu, sdy,  off);
        sdxx += __shfl_down_sync(0xffffffffu, sdxx, off);
        sdyy += __shfl_down_sync(0xffffffffu, sdyy, off);
        sdxy += __shfl_down_sync(0xffffffffu, sdxy, off);
    }

    __shared__ float s_red[8][6];
    if (lane == 0) {
        s_red[warp][0] = e;    s_red[warp][1] = sdx;  s_red[warp][2] = sdy;
        s_red[warp][3] = sdxx; s_red[warp][4] = sdyy; s_red[warp][5] = sdxy;
    }
    __syncthreads();

    if (tid == 0) {
        float S = 0.f, Sx = 0.f, Sy = 0.f, Sxx = 0.f, Syy = 0.f, Sxy = 0.f;
        #pragma unroll
        for (int w = 0; w < 8; w++) {
            S   += s_red[w][0]; Sx  += s_red[w][1]; Sy  += s_red[w][2];
            Sxx += s_red[w][3]; Syy += s_red[w][4]; Sxy += s_red[w][5];
        }
        float inv = 1.0f / S;
        float mdx = Sx * inv;             // E[dx]
        float mdy = Sy * inv;             // E[dy]
        float var_xx = Sxx * inv - mdx * mdx;
        float var_yy = Syy * inv - mdy * mdy;
        float cov_xy = Sxy * inv - mdx * mdy;

        float x_mean = (float)x0 + mdx;
        float y_mean = (float)y0 + mdy;

        // coords (B,C,2) at [0, 4096)
        out[bc * 2 + 0] = x_mean * (1.0f / (W - 1));
        out[bc * 2 + 1] = y_mean * (1.0f / (H - 1));
        // cov (B,C,2,2) at [4096, 12288)
        float* covp = out + 2 * 2048 + bc * 4;
        covp[0] = var_xx;
        covp[1] = cov_xy;
        covp[2] = cov_xy;
        covp[3] = var_yy;
        // spread (B,C,1) at [12288, 14336)
        out[2 * 2048 + 4 * 2048 + bc] = var_xx + var_yy;
    }
}

extern "C" void kernel_launch(void* const* d_in, const int* in_sizes, int n_in,
                              void* d_out, int out_size)
{
    const float* heatmap = (const float*)d_in[0];
    float* out = (float*)d_out;
    int n_bc = in_sizes[0] / HW;   // 32*64 = 2048
    softargmax_kernel<<<n_bc, NTHREADS>>>(heatmap, out, n_bc);
}

// round 16
// speedup vs baseline: 1.0800x; 1.0004x over previous
#include <cuda_runtime.h>
#include <math.h>

// SoftArgmax over (B=32, C=64, H=256, W=256) fp32 heatmap.
// Outputs concatenated: coords (B,C,2) | cov (B,C,2,2) | spread (B,C,1)
//   = 4096 + 8192 + 2048 = 14336 floats.
//
// FINAL FORM (best measured: 80.38us; reproduced 5x at 80.4-81.4us, sigma
// ~0.4us, plus one 86.8us DVFS outlier). One block per (b,c), 256 threads,
// occ 8 (64 warps/SM). The scan streams 536 MB at ~6.7 TB/s, pinned at the
// B300 full-chip LTS throughput cap (~6300 B/cyc, path-independent) —
// invariant across ILP / occupancy / launch-structure variants (R4-R7).
// Hard floor ~79.2us; no measured alternative came closer.
// Phase 1: float4 argmax scan, lowest-index tie-break (jnp.argmax semantics).
// Phase 2: masked softmax over the clamped 16x16 window, moments relative
// to (x0,y0) for fp32 accuracy; window reloads hit L2.

#define HW 65536
#define W 256
#define H 256
#define HALF 8
#define NTHREADS 256
#define INV_TEMP 100.0f   // 1 / 0.01

__global__ __launch_bounds__(NTHREADS)
void softargmax_kernel(const float* __restrict__ heatmap, float* __restrict__ out, int n_bc)
{
    int bc = blockIdx.x;
    if (bc >= n_bc) return;
    const float* base = heatmap + (size_t)bc * HW;

    int tid  = threadIdx.x;
    int lane = tid & 31;
    int warp = tid >> 5;

    // ---------------- Phase 1: argmax (lowest-index tie-break) ----------------
    float best = -INFINITY;
    int   bidx = 0;

    const float4* p4 = (const float4*)base;
    #pragma unroll 4
    for (int i = tid; i < HW / 4; i += NTHREADS) {
        float4 v = __ldg(&p4[i]);
        int ib = i * 4;
        if (v.x > best || (v.x == best && ib + 0 < bidx)) { best = v.x; bidx = ib + 0; }
        if (v.y > best || (v.y == best && ib + 1 < bidx)) { best = v.y; bidx = ib + 1; }
        if (v.z > best || (v.z == best && ib + 2 < bidx)) { best = v.z; bidx = ib + 2; }
        if (v.w > best || (v.w == best && ib + 3 < bidx)) { best = v.w; bidx = ib + 3; }
    }

    // warp reduction
    #pragma unroll
    for (int off = 16; off > 0; off >>= 1) {
        float ov = __shfl_down_sync(0xffffffffu, best, off);
        int   oi = __shfl_down_sync(0xffffffffu, bidx, off);
        if (ov > best || (ov == best && oi < bidx)) { best = ov; bidx = oi; }
    }

    __shared__ float s_wval[8];
    __shared__ int   s_widx[8];
    __shared__ int   s_argmax;
    __shared__ float s_vmax;

    if (lane == 0) { s_wval[warp] = best; s_widx[warp] = bidx; }
    __syncthreads();

    if (tid == 0) {
        float bv = s_wval[0]; int bi = s_widx[0];
        #pragma unroll
        for (int w = 1; w < 8; w++) {
            float ov = s_wval[w]; int oi = s_widx[w];
            if (ov > bv || (ov == bv && oi < bi)) { bv = ov; bi = oi; }
        }
        s_argmax = bi;
        s_vmax   = bv;
    }
    __syncthreads();

    int   idx  = s_argmax;
    float vmax = s_vmax;
    int x0 = idx & (W - 1);
    int y0 = idx >> 8;

    int xmin = max(x0 - HALF, 0);
    int xmax = min(x0 + HALF, W);
    int ymin = max(y0 - HALF, 0);
    int ymax = min(y0 + HALF, H);
    int wx = xmax - xmin;
    int wy = ymax - ymin;

    // ---------------- Phase 2: windowed softmax moments ----------------
    // thread (ly, lx) = (tid/16, tid%16) covers window cell (ymin+ly, xmin+lx)
    int lx = tid & 15;
    int ly = tid >> 4;

    float e = 0.f, sdx = 0.f, sdy = 0.f, sdxx = 0.f, sdyy = 0.f, sdxy = 0.f;
    if (lx < wx && ly < wy) {
        int gx = xmin + lx;
        int gy = ymin + ly;
        float v = __ldg(&base[gy * W + gx]);
        float w8 = expf((v - vmax) * INV_TEMP);
        float dx = (float)(gx - x0);
        float dy = (float)(gy - y0);
        e    = w8;
        sdx  = w8 * dx;
        sdy  = w8 * dy;
        sdxx = w8 * dx * dx;
        sdyy = w8 * dy * dy;
        sdxy = w8 * dx * dy;
    }

    // reduce 6 sums: warp shuffle then cross-warp via shared
    #pragma unroll
    for (int off = 16; off > 0; off >>= 1) {
        e    += __shfl_down_sync(0xffffffffu, e,    off);
        sdx  += __shfl_down_sync(0xffffffffu, sdx,  off);
        sdy  += __shfl_down_sync(0xffffffffu, sdy,  off);
        sdxx += __shfl_down_sync(0xffffffffu, sdxx, off);
        sdyy += __shfl_down_sync(0xffffffffu, sdyy, off);
        sdxy += __shfl_down_sync(0xffffffffu, sdxy, off);
    }

    __shared__ float s_red[8][6];
    if (lane == 0) {
        s_red[warp][0] = e;    s_red[warp][1] = sdx;  s_red[warp][2] = sdy;
        s_red[warp][3] = sdxx; s_red[warp][4] = sdyy; s_red[warp][5] = sdxy;
    }
    __syncthreads();

    if (tid == 0) {
        float S = 0.f, Sx = 0.f, Sy = 0.f, Sxx = 0.f, Syy = 0.f, Sxy = 0.f;
        #pragma unroll
        for (int w = 0; w < 8; w++) {
            S   += s_red[w][0]; Sx  += s_red[w][1]; Sy  += s_red[w][2];
            Sxx += s_red[w][3]; Syy += s_red[w][4]; Sxy += s_red[w][5];
        }
        float inv = 1.0f / S;
        float mdx = Sx * inv;             // E[dx]
        float mdy = Sy * inv;             // E[dy]
        float var_xx = Sxx * inv - mdx * mdx;
        float var_yy = Syy * inv - mdy * mdy;
        float cov_xy = Sxy * inv - mdx * mdy;

        float x_mean = (float)x0 + mdx;
        float y_mean = (float)y0 + mdy;

        // coords (B,C,2) at [0, 4096)
        out[bc * 2 + 0] = x_mean * (1.0f / (W - 1));
        out[bc * 2 + 1] = y_mean * (1.0f / (H - 1));
        // cov (B,C,2,2) at [4096, 12288)
        float* covp = out + 2 * 2048 + bc * 4;
        covp[0] = var_xx;
        covp[1] = cov_xy;
        covp[2] = cov_xy;
        covp[3] = var_yy;
        // spread (B,C,1) at [12288, 14336)
        out[2 * 2048 + 4 * 2048 + bc] = var_xx + var_yy;
    }
}

extern "C" void kernel_launch(void* const* d_in, const int* in_sizes, int n_in,
                              void* d_out, int out_size)
{
    const float* heatmap = (const float*)d_in[0];
    float* out = (float*)d_out;
    int n_bc = in_sizes[0] / HW;   // 32*64 = 2048
    softargmax_kernel<<<n_bc, NTHREADS>>>(heatmap, out, n_bc);
}